// round 13
// baseline (speedup 1.0000x reference)
#include <cuda_runtime.h>
#include <cuda_fp16.h>

// Fused MultiAttention, two-kernel split:
//  A: QKV proj + causal attention -> fp16 scratch (M=32/warp register blocking,
//     K stays in registers via C-frag->B-frag identity)
//  B: FC GEMM [rows,256]x[256,256]+bias from scratch (M=32/warp, N=128/warp)
// B=32768, T=8, D=256, H=4, DH=64.  fp16 mma.sync, fp32 accumulate.

#define NH      4
#define DMODEL  256
#define MTA     256   // rows per CTA, kernel A (32 batches)
#define MTB     128   // rows per CTA, kernel B
#define XS      264   // x/o smem row stride in halves (528 B, conflict-free ldmatrix)
#define KV      72    // v smem row stride in halves (144 B)
#define SMEM_A  204800   // xs 135168 + ws 32768 + vs 36864
#define SMEM_B  198656   // os 67584 + wsf 131072

// Weights in mma-B-fragment layout (built by prep_kernel each launch).
// QKV: [h][nt(8)][kt(16)][lane(32)]  uint2 {pack(Wk,Wk1), pack(Wk8,Wk9)}
// FC:  [h][nt(32)][kt(4)][lane(32)]   (h = k-chunk of DHEAD)
static __device__ __align__(16) uint2 g_wq[16384];
static __device__ __align__(16) uint2 g_wk[16384];
static __device__ __align__(16) uint2 g_wv[16384];
static __device__ __align__(16) uint2 g_wfc[16384];
// fp16 attention-output scratch [262144][256]
static __device__ __align__(16) __half g_oscr[(size_t)262144 * 256];

__device__ __forceinline__ unsigned pack2(float a, float b) {
    __half2 h = __floats2half2_rn(a, b);
    return *reinterpret_cast<unsigned*>(&h);
}

__device__ __forceinline__ void ldm4(unsigned r[4], const void* p) {
    unsigned a = (unsigned)__cvta_generic_to_shared(p);
    asm volatile("ldmatrix.sync.aligned.m8n8.x4.shared.b16 {%0,%1,%2,%3}, [%4];"
                 : "=r"(r[0]), "=r"(r[1]), "=r"(r[2]), "=r"(r[3]) : "r"(a));
}

__device__ __forceinline__ void ldm4t(unsigned r[4], const void* p) {
    unsigned a = (unsigned)__cvta_generic_to_shared(p);
    asm volatile("ldmatrix.sync.aligned.m8n8.x4.trans.shared.b16 {%0,%1,%2,%3}, [%4];"
                 : "=r"(r[0]), "=r"(r[1]), "=r"(r[2]), "=r"(r[3]) : "r"(a));
}

__device__ __forceinline__ void mma16816(float c[4], const unsigned a[4],
                                         unsigned b0, unsigned b1) {
    asm volatile("mma.sync.aligned.m16n8k16.row.col.f32.f16.f16.f32 "
                 "{%0,%1,%2,%3}, {%4,%5,%6,%7}, {%8,%9}, {%0,%1,%2,%3};"
                 : "+f"(c[0]), "+f"(c[1]), "+f"(c[2]), "+f"(c[3])
                 : "r"(a[0]), "r"(a[1]), "r"(a[2]), "r"(a[3]), "r"(b0), "r"(b1));
}

// ---------------- weight prep: fp32 -> fp16 B-fragment layout ----------------
__global__ void prep_kernel(const float* __restrict__ Wq, const float* __restrict__ Wk,
                            const float* __restrict__ Wv, const float* __restrict__ Wfc) {
    int t = blockIdx.x * 256 + threadIdx.x;   // 0..16383
    int lane   = t & 31;
    int n_half = lane >> 2;
    int k_off  = (lane & 3) << 1;

    {   // QKV: t = h*4096 + nt*512 + kt*32 + lane
        int h  = t >> 12;
        int nt = (t >> 9) & 7;
        int kt = (t >> 5) & 15;
        int n  = nt * 8 + n_half;
        int k  = kt * 16 + k_off;
        const float* W3[3] = {Wq, Wk, Wv};
        uint2* G3[3] = {g_wq, g_wk, g_wv};
        #pragma unroll
        for (int w = 0; w < 3; ++w) {
            const float* base = W3[w] + (size_t)h * (DMODEL * 64) + n;
            uint2 o;
            o.x = pack2(base[(size_t)k * 64],       base[(size_t)(k + 1) * 64]);
            o.y = pack2(base[(size_t)(k + 8) * 64], base[(size_t)(k + 9) * 64]);
            G3[w][t] = o;
        }
    }
    {   // FC: t = h*4096 + nt*128 + kt*32 + lane
        int h  = t >> 12;
        int nt = (t >> 7) & 31;
        int kt = (t >> 5) & 3;
        int n  = nt * 8 + n_half;
        int k  = h * 64 + kt * 16 + k_off;
        uint2 o;
        o.x = pack2(Wfc[(size_t)k * 256 + n],       Wfc[(size_t)(k + 1) * 256 + n]);
        o.y = pack2(Wfc[(size_t)(k + 8) * 256 + n], Wfc[(size_t)(k + 9) * 256 + n]);
        g_wfc[t] = o;
    }
}

// ---------------- helpers ----------------
__device__ __forceinline__ void stage(uint2* ws, const uint2* src) {
    __syncthreads();
    uint4* d = reinterpret_cast<uint4*>(ws);
    const uint4* s = reinterpret_cast<const uint4*>(src);
    for (int i = threadIdx.x; i < 2048; i += 256) d[i] = s[i];
    __syncthreads();
}

// [32,256] @ [256,64] per warp: 2 A-tiles share every B fragment.
__device__ __forceinline__ void gemm2(float acc[2][8][4], const __half* arow,
                                      const uint2* ws, int lane) {
    #pragma unroll
    for (int mt = 0; mt < 2; ++mt)
        #pragma unroll
        for (int nt = 0; nt < 8; ++nt)
            acc[mt][nt][0] = acc[mt][nt][1] = acc[mt][nt][2] = acc[mt][nt][3] = 0.f;
    #pragma unroll 4
    for (int kt = 0; kt < 16; ++kt) {
        unsigned a0[4], a1[4];
        ldm4(a0, arow + kt * 16);
        ldm4(a1, arow + 16 * XS + kt * 16);
        const uint2* wp = ws + kt * 32 + lane;
        #pragma unroll
        for (int nt = 0; nt < 8; ++nt) {
            uint2 b = wp[nt * 512];
            mma16816(acc[0][nt], a0, b.x, b.y);
            mma16816(acc[1][nt], a1, b.x, b.y);
        }
    }
}

__device__ __forceinline__ void addbias(float acc[2][8][4], const float* __restrict__ bias,
                                        int m2) {
    #pragma unroll
    for (int nt = 0; nt < 8; ++nt) {
        float2 bb = *reinterpret_cast<const float2*>(bias + nt * 8 + m2);
        #pragma unroll
        for (int mt = 0; mt < 2; ++mt) {
            acc[mt][nt][0] += bb.x; acc[mt][nt][1] += bb.y;
            acc[mt][nt][2] += bb.x; acc[mt][nt][3] += bb.y;
        }
    }
}

// causal softmax over one 8-wide score row spread 2/lane across a lane-quad
__device__ __forceinline__ void softmax2(float s0, float s1, int t, int j0,
                                         float& p0, float& p1) {
    float v0 = (j0     <= t) ? s0 : -1e30f;
    float v1 = (j0 + 1 <= t) ? s1 : -1e30f;
    float m = fmaxf(v0, v1);
    m = fmaxf(m, __shfl_xor_sync(0xffffffffu, m, 1));
    m = fmaxf(m, __shfl_xor_sync(0xffffffffu, m, 2));
    float e0 = (j0     <= t) ? __expf(v0 - m) : 0.f;
    float e1 = (j0 + 1 <= t) ? __expf(v1 - m) : 0.f;
    float s = e0 + e1;
    s += __shfl_xor_sync(0xffffffffu, s, 1);
    s += __shfl_xor_sync(0xffffffffu, s, 2);
    float r = 1.f / s;
    p0 = e0 * r;
    p1 = e1 * r;
}

// ---------------- kernel A: QKV + attention -> scratch ----------------
__global__ void __launch_bounds__(256, 1)
attn_kernel(const float* __restrict__ x,
            const float* __restrict__ bq, const float* __restrict__ bk,
            const float* __restrict__ bv)
{
    extern __shared__ char smem[];
    __half* xs = reinterpret_cast<__half*>(smem);            // [256][264] 135168 B
    uint2*  ws = reinterpret_cast<uint2*>(smem + 135168);    // 4096 uint2  32768 B
    __half* vs = reinterpret_cast<__half*>(smem + 167936);   // [256][72]   36864 B

    const int tid  = threadIdx.x;
    const int lane = tid & 31;
    const int warp = tid >> 5;
    const int g    = lane >> 2;
    const int m2   = (lane & 3) << 1;
    const int row0 = warp << 5;          // warp's 32-row window
    const size_t m0 = (size_t)blockIdx.x * MTA;

    // x tile -> fp16 smem
    {
        const float4* xg = reinterpret_cast<const float4*>(x + m0 * DMODEL);
        for (int i = tid; i < MTA * 64; i += 256) {
            float4 v = xg[i];
            __half2* d = reinterpret_cast<__half2*>(xs + (i >> 6) * XS + (i & 63) * 4);
            d[0] = __floats2half2_rn(v.x, v.y);
            d[1] = __floats2half2_rn(v.z, v.w);
        }
    }
    // first stage() below syncs before xs is read

    const __half* arow = xs + (row0 + (lane & 15)) * XS + ((lane >> 4) << 3);

    #pragma unroll 1
    for (int h = 0; h < NH; ++h) {
        unsigned qf[2][4][4];            // Q A-frags per m-tile, pre-scaled

        // ---- Q ----
        stage(ws, g_wq + h * 4096);
        {
            float qa[2][8][4];
            gemm2(qa, arow, ws, lane);
            #pragma unroll
            for (int nt = 0; nt < 8; ++nt) {
                float2 bb = *reinterpret_cast<const float2*>(bq + h * 64 + nt * 8 + m2);
                #pragma unroll
                for (int mt = 0; mt < 2; ++mt) {
                    qa[mt][nt][0] = (qa[mt][nt][0] + bb.x) * 0.125f;
                    qa[mt][nt][1] = (qa[mt][nt][1] + bb.y) * 0.125f;
                    qa[mt][nt][2] = (qa[mt][nt][2] + bb.x) * 0.125f;
                    qa[mt][nt][3] = (qa[mt][nt][3] + bb.y) * 0.125f;
                }
            }
            #pragma unroll
            for (int mt = 0; mt < 2; ++mt)
                #pragma unroll
                for (int kt = 0; kt < 4; ++kt) {
                    qf[mt][kt][0] = pack2(qa[mt][2*kt][0],     qa[mt][2*kt][1]);
                    qf[mt][kt][1] = pack2(qa[mt][2*kt][2],     qa[mt][2*kt][3]);
                    qf[mt][kt][2] = pack2(qa[mt][2*kt + 1][0], qa[mt][2*kt + 1][1]);
                    qf[mt][kt][3] = pack2(qa[mt][2*kt + 1][2], qa[mt][2*kt + 1][3]);
                }
        }

        // ---- K (stays in registers) + S = Q K^T ----
        float sa[2][2][4];
        stage(ws, g_wk + h * 4096);
        {
            float ka[2][8][4];
            gemm2(ka, arow, ws, lane);
            addbias(ka, bk + h * 64, m2);
            #pragma unroll
            for (int mt = 0; mt < 2; ++mt) {
                sa[mt][0][0] = sa[mt][0][1] = sa[mt][0][2] = sa[mt][0][3] = 0.f;
                sa[mt][1][0] = sa[mt][1][1] = sa[mt][1][2] = sa[mt][1][3] = 0.f;
                #pragma unroll
                for (int kt = 0; kt < 4; ++kt) {
                    // C-frag(K) == B-frag(K^T) lane-for-lane:
                    unsigned b0 = pack2(ka[mt][2*kt][0],     ka[mt][2*kt][1]);
                    unsigned b1 = pack2(ka[mt][2*kt + 1][0], ka[mt][2*kt + 1][1]);
                    mma16816(sa[mt][0], qf[mt][kt], b0, b1);     // kv rows 0-7
                    unsigned c0 = pack2(ka[mt][2*kt][2],     ka[mt][2*kt][3]);
                    unsigned c1 = pack2(ka[mt][2*kt + 1][2], ka[mt][2*kt + 1][3]);
                    mma16816(sa[mt][1], qf[mt][kt], c0, c1);     // kv rows 8-15
                }
            }
        }

        // ---- V -> smem (per-warp private rows) ----
        stage(ws, g_wv + h * 4096);
        {
            float va[2][8][4];
            gemm2(va, arow, ws, lane);
            #pragma unroll
            for (int mt = 0; mt < 2; ++mt)
                #pragma unroll
                for (int nt = 0; nt < 8; ++nt) {
                    int c = nt * 8 + m2;
                    float2 bb = *reinterpret_cast<const float2*>(bv + h * 64 + c);
                    int rb = row0 + mt * 16 + g;
                    *reinterpret_cast<__half2*>(vs + rb * KV + c) =
                        __floats2half2_rn(va[mt][nt][0] + bb.x, va[mt][nt][1] + bb.y);
                    *reinterpret_cast<__half2*>(vs + (rb + 8) * KV + c) =
                        __floats2half2_rn(va[mt][nt][2] + bb.x, va[mt][nt][3] + bb.y);
                }
            __syncwarp();
        }

        // ---- per m-tile: softmax, O = P V, store to scratch ----
        #pragma unroll
        for (int mt = 0; mt < 2; ++mt) {
            unsigned pf[4];
            {
                float p00, p01, p10, p11;
                softmax2(sa[mt][0][0], sa[mt][0][1], g, m2, p00, p01);
                softmax2(sa[mt][1][2], sa[mt][1][3], g, m2, p10, p11);
                pf[0] = pack2(p00, p01);
                pf[1] = 0u;
                pf[2] = 0u;
                pf[3] = pack2(p10, p11);
            }
            float oa[8][4];
            #pragma unroll
            for (int i = 0; i < 8; ++i)
                oa[i][0] = oa[i][1] = oa[i][2] = oa[i][3] = 0.f;
            const __half* vrow = vs + (row0 + mt * 16 + (lane & 15)) * KV
                               + ((lane >> 4) << 3);
            #pragma unroll
            for (int i2 = 0; i2 < 4; ++i2) {
                unsigned vb[4];
                ldm4t(vb, vrow + i2 * 16);
                mma16816(oa[2*i2],     pf, vb[0], vb[1]);
                mma16816(oa[2*i2 + 1], pf, vb[2], vb[3]);
            }
            __half* s0 = g_oscr + (m0 + row0 + mt * 16 + g) * 256 + h * 64;
            __half* s1 = s0 + (size_t)8 * 256;
            #pragma unroll
            for (int nt = 0; nt < 8; ++nt) {
                int c = nt * 8 + m2;
                *reinterpret_cast<__half2*>(s0 + c) = __floats2half2_rn(oa[nt][0], oa[nt][1]);
                *reinterpret_cast<__half2*>(s1 + c) = __floats2half2_rn(oa[nt][2], oa[nt][3]);
            }
        }
        __syncwarp();   // vs reads done before next head's V overwrite
    }
}

// ---------------- kernel B: out = scratch @ Wfc + bfc ----------------
__global__ void __launch_bounds__(256, 1)
fc_kernel(const float* __restrict__ bfc, float* __restrict__ out)
{
    extern __shared__ char smem[];
    __half* os  = reinterpret_cast<__half*>(smem);           // [128][264] 67584 B
    uint2*  wsf = reinterpret_cast<uint2*>(smem + 67584);    // 16384 uint2 131072 B

    const int tid  = threadIdx.x;
    const int lane = tid & 31;
    const int warp = tid >> 5;
    const int g    = lane >> 2;
    const int m2   = (lane & 3) << 1;
    const int rg   = warp >> 1;          // row group (32 rows)
    const int ch   = warp & 1;           // col half (128 cols)
    const size_t m0 = (size_t)blockIdx.x * MTB;

    // stage full FC weight (128 KB)
    {
        uint4* d = reinterpret_cast<uint4*>(wsf);
        const uint4* s = reinterpret_cast<const uint4*>(g_wfc);
        for (int i = tid; i < 8192; i += 256) d[i] = s[i];
    }
    // O tile -> smem (fp16 passthrough)
    {
        for (int i = tid; i < MTB * 32; i += 256) {
            int row = i >> 5, c = i & 31;
            *reinterpret_cast<uint4*>(os + row * XS + c * 8) =
                *reinterpret_cast<const uint4*>(g_oscr + (m0 + row) * 256 + c * 8);
        }
    }
    __syncthreads();

    const __half* arow = os + (rg * 32 + (lane & 15)) * XS + ((lane >> 4) << 3);

    float acc[2][16][4];
    #pragma unroll
    for (int mt = 0; mt < 2; ++mt)
        #pragma unroll
        for (int nt = 0; nt < 16; ++nt)
            acc[mt][nt][0] = acc[mt][nt][1] = acc[mt][nt][2] = acc[mt][nt][3] = 0.f;

    #pragma unroll 4
    for (int hk = 0; hk < 16; ++hk) {    // K=256 in 16-chunks
        unsigned a0[4], a1[4];
        ldm4(a0, arow + hk * 16);
        ldm4(a1, arow + 16 * XS + hk * 16);
        const uint2* wp = wsf + (hk >> 2) * 4096 + (ch * 16) * 128 + (hk & 3) * 32 + lane;
        #pragma unroll
        for (int nt = 0; nt < 16; ++nt) {
            uint2 b = wp[nt * 128];
            mma16816(acc[0][nt], a0, b.x, b.y);
            mma16816(acc[1][nt], a1, b.x, b.y);
        }
    }

    #pragma unroll
    for (int mt = 0; mt < 2; ++mt) {
        float* o0 = out + (m0 + rg * 32 + mt * 16 + g) * DMODEL + ch * 128;
        float* o1 = o0 + (size_t)8 * DMODEL;
        #pragma unroll
        for (int nt = 0; nt < 16; ++nt) {
            int c = nt * 8 + m2;
            float2 bb = *reinterpret_cast<const float2*>(bfc + ch * 128 + c);
            *reinterpret_cast<float2*>(o0 + c) =
                make_float2(acc[mt][nt][0] + bb.x, acc[mt][nt][1] + bb.y);
            *reinterpret_cast<float2*>(o1 + c) =
                make_float2(acc[mt][nt][2] + bb.x, acc[mt][nt][3] + bb.y);
        }
    }
}

extern "C" void kernel_launch(void* const* d_in, const int* in_sizes, int n_in,
                              void* d_out, int out_size) {
    const float* x   = (const float*)d_in[0];
    const float* Wq  = (const float*)d_in[1];
    const float* bq  = (const float*)d_in[2];
    const float* Wk  = (const float*)d_in[3];
    const float* bk  = (const float*)d_in[4];
    const float* Wv  = (const float*)d_in[5];
    const float* bv  = (const float*)d_in[6];
    const float* Wfc = (const float*)d_in[7];
    const float* bfc = (const float*)d_in[8];
    float* out = (float*)d_out;

    cudaFuncSetAttribute(attn_kernel, cudaFuncAttributeMaxDynamicSharedMemorySize, SMEM_A);
    cudaFuncSetAttribute(fc_kernel,   cudaFuncAttributeMaxDynamicSharedMemorySize, SMEM_B);

    int rows = in_sizes[0] / DMODEL;     // 262144

    prep_kernel<<<64, 256>>>(Wq, Wk, Wv, Wfc);
    attn_kernel<<<rows / MTA, 256, SMEM_A>>>(x, bq, bk, bv);
    fc_kernel<<<rows / MTB, 256, SMEM_B>>>(bfc, out);
}